// round 9
// baseline (speedup 1.0000x reference)
#include <cuda_runtime.h>
#include <cuda_bf16.h>
#include <cstdint>

#define FULLMASK 0xffffffffu

// ---------------- scratch (device globals; no allocations) -------------------
__device__ float g_gates[2048 * 768];          // pre-activation gates (i|g|o)
__device__ float g_ww[2048 * 1024];            // write-attn RAW logits
__device__ float2 g_wstat[2048];               // per-row (max, 1/sumexp)
__device__ float g_erase[2048 * 32];
__device__ float g_add[2048 * 32];
__device__ float g_gate_bias[1024];            // indexed by ORIGINAL 1024 gate idx
__device__ float g_out_bias[256];

// bf16 split buffers (K expanded 256 -> 768: A=[hi|lo|hi], B=[hi|hi|lo])
__device__ __nv_bfloat16 g_xs[2048 * 768];
__device__ __nv_bfloat16 g_hs[2048 * 768];
__device__ __nv_bfloat16 g_Bih[768 * 768];     // W_ih gate rows (i|g|o)
__device__ __nv_bfloat16 g_Bcomb[1408 * 768];  // [W_wattn(1024) | W_er|W_ad|W_out|pad]

// fast transcendentals: ~1e-6 rel err (MUFU-based), far cheaper than libm
__device__ __forceinline__ float sigm_fast(float x)
{
    return __fdividef(1.f, 1.f + __expf(-x));
}
__device__ __forceinline__ float tanh_fast(float x)
{
    const float e = __expf(2.f * x);
    return 1.f - __fdividef(2.f, e + 1.f);
}

// ---------------- PTX helpers -------------------------------------------------
__device__ __forceinline__ void ldsm4(uint32_t& r0, uint32_t& r1, uint32_t& r2,
                                      uint32_t& r3, uint32_t addr)
{
    asm volatile("ldmatrix.sync.aligned.m8n8.x4.shared.b16 {%0,%1,%2,%3}, [%4];"
                 : "=r"(r0), "=r"(r1), "=r"(r2), "=r"(r3) : "r"(addr));
}
__device__ __forceinline__ void mma16816(float& d0, float& d1, float& d2, float& d3,
                                         uint32_t a0, uint32_t a1, uint32_t a2, uint32_t a3,
                                         uint32_t b0, uint32_t b1)
{
    asm volatile(
        "mma.sync.aligned.m16n8k16.row.col.f32.bf16.bf16.f32 "
        "{%0,%1,%2,%3}, {%4,%5,%6,%7}, {%8,%9}, {%0,%1,%2,%3};"
        : "+f"(d0), "+f"(d1), "+f"(d2), "+f"(d3)
        : "r"(a0), "r"(a1), "r"(a2), "r"(a3), "r"(b0), "r"(b1));
}
__device__ __forceinline__ void cpasync16(uint32_t dst, const void* src)
{
    asm volatile("cp.async.cg.shared.global [%0], [%1], 16;" :: "r"(dst), "l"(src));
}
__device__ __forceinline__ void cpcommit() { asm volatile("cp.async.commit_group;"); }
__device__ __forceinline__ void cpwait3() { asm volatile("cp.async.wait_group 3;"); }

__device__ __forceinline__ uint32_t packbf2(float a, float b)
{
    __nv_bfloat162 t = __floats2bfloat162_rn(a, b);
    return *reinterpret_cast<uint32_t*>(&t);
}

// ---------------- k0: setup — softmax(b_rattn), rd, folded biases -------------
__global__ __launch_bounds__(256) void setup_kernel(
    const float* __restrict__ b_rattn, const float* __restrict__ memory,
    const float* __restrict__ W_ih, const float* __restrict__ b_ih,
    const float* __restrict__ b_hh, const float* __restrict__ W_out,
    const float* __restrict__ b_out)
{
    __shared__ float wr[1024];
    __shared__ float red[32];
    __shared__ float bc;
    __shared__ float part[8 * 32];
    __shared__ float rd_s[32];
    const int t = threadIdx.x;
    const int lane = t & 31, w = t >> 5;

    float mx = -1e30f;
    for (int i = t; i < 1024; i += 256) { float v = b_rattn[i]; wr[i] = v; mx = fmaxf(mx, v); }
#pragma unroll
    for (int o = 16; o; o >>= 1) mx = fmaxf(mx, __shfl_xor_sync(FULLMASK, mx, o));
    if (lane == 0) red[w] = mx;
    __syncthreads();
    if (t == 0) { float m = red[0]; for (int i = 1; i < 8; i++) m = fmaxf(m, red[i]); bc = m; }
    __syncthreads();
    mx = bc;
    float s = 0.f;
    for (int i = t; i < 1024; i += 256) { float e = __expf(wr[i] - mx); wr[i] = e; s += e; }
#pragma unroll
    for (int o = 16; o; o >>= 1) s += __shfl_xor_sync(FULLMASK, s, o);
    __syncthreads();
    if (lane == 0) red[w] = s;
    __syncthreads();
    if (t == 0) { float ss = 0.f; for (int i = 0; i < 8; i++) ss += red[i]; bc = ss; }
    __syncthreads();
    const float inv = 1.f / bc;
    for (int i = t; i < 1024; i += 256) wr[i] *= inv;
    __syncthreads();

    {
        const int d = lane, pp = w;
        float acc = 0.f;
        const int m0 = pp * 128;
        for (int m = m0; m < m0 + 128; m++) acc += wr[m] * memory[m * 32 + d];
        part[pp * 32 + d] = acc;
    }
    __syncthreads();
    if (t < 32) { float r = 0.f; for (int p = 0; p < 8; p++) r += part[p * 32 + t]; rd_s[t] = r; }
    __syncthreads();

    for (int j = t; j < 1024; j += 256) {
        float g = b_ih[j] + b_hh[j];
        const float* wp = W_ih + (size_t)j * 288 + 256;
#pragma unroll
        for (int d = 0; d < 32; d++) g += wp[d] * rd_s[d];
        g_gate_bias[j] = g;
    }
    {
        float g = b_out[t];
        const float* wp = W_out + (size_t)t * 288 + 256;
#pragma unroll
        for (int d = 0; d < 32; d++) g += wp[d] * rd_s[d];
        g_out_bias[t] = g;
    }
}

// ---------------- vectorized split writers ------------------------------------
__device__ __forceinline__ void splitA4(__nv_bfloat16* dst, float4 v)
{
    const float h0 = __bfloat162float(__float2bfloat16_rn(v.x));
    const float h1 = __bfloat162float(__float2bfloat16_rn(v.y));
    const float h2 = __bfloat162float(__float2bfloat16_rn(v.z));
    const float h3 = __bfloat162float(__float2bfloat16_rn(v.w));
    const uint2 hi = make_uint2(packbf2(v.x, v.y), packbf2(v.z, v.w));
    const uint2 lo = make_uint2(packbf2(v.x - h0, v.y - h1), packbf2(v.z - h2, v.w - h3));
    *(uint2*)(dst) = hi;
    *(uint2*)(dst + 256) = lo;
    *(uint2*)(dst + 512) = hi;
}
__device__ __forceinline__ void splitB4(__nv_bfloat16* dst, float4 v)
{
    const float h0 = __bfloat162float(__float2bfloat16_rn(v.x));
    const float h1 = __bfloat162float(__float2bfloat16_rn(v.y));
    const float h2 = __bfloat162float(__float2bfloat16_rn(v.z));
    const float h3 = __bfloat162float(__float2bfloat16_rn(v.w));
    const uint2 hi = make_uint2(packbf2(v.x, v.y), packbf2(v.z, v.w));
    const uint2 lo = make_uint2(packbf2(v.x - h0, v.y - h1), packbf2(v.z - h2, v.w - h3));
    *(uint2*)(dst) = hi;
    *(uint2*)(dst + 256) = hi;
    *(uint2*)(dst + 512) = lo;
}

// ---------------- k1: convert x + all weights (one launch, x4 vectorized) ----
__global__ __launch_bounds__(256) void conv_all_kernel(
    const float* __restrict__ x, const float* __restrict__ W_ih,
    const float* __restrict__ W_wattn, const float* __restrict__ W_er,
    const float* __restrict__ W_ad, const float* __restrict__ W_out)
{
    const int vr = blockIdx.x * 4 + (threadIdx.x >> 6);
    const int k = (threadIdx.x & 63) * 4;
    if (vr < 2048) {
        splitA4(g_xs + (size_t)vr * 768 + k, *(const float4*)(x + (size_t)vr * 256 + k));
    } else if (vr < 2816) {
        const int r = vr - 2048;
        const int orig = r + (r >= 256 ? 256 : 0);
        splitB4(g_Bih + (size_t)r * 768 + k, *(const float4*)(W_ih + (size_t)orig * 288 + k));
    } else if (vr < 3840) {
        const int rw = vr - 2816;
        splitB4(g_Bcomb + (size_t)rw * 768 + k, *(const float4*)(W_wattn + (size_t)rw * 256 + k));
    } else {
        const int rh = vr - 3840;
        float4 v = make_float4(0.f, 0.f, 0.f, 0.f);
        if (rh < 32)       v = *(const float4*)(W_er + (size_t)rh * 256 + k);
        else if (rh < 64)  v = *(const float4*)(W_ad + (size_t)(rh - 32) * 256 + k);
        else if (rh < 320) v = *(const float4*)(W_out + (size_t)(rh - 64) * 288 + k);
        splitB4(g_Bcomb + (size_t)(1024 + rh) * 768 + k, v);
    }
}

// ---------------- bf16 MMA GEMM: 64(M) x 128(N), K'=768 ----------------------
// 5-stage static-smem cp.async pipeline, K-chunk 16, wait_group 3
// MODE 0: A=g_xs, B=g_Bih (N=768),   out g_gates + gate_bias(remap)
// MODE 1: A=g_hs, B=g_Bcomb(N=1408), n<1024 -> g_ww logits + b_wattn; else head
template <int MODE>
__global__ __launch_bounds__(256, 2) void mma_gemm(
    const __nv_bfloat16* __restrict__ A, const __nv_bfloat16* __restrict__ B,
    const float* __restrict__ bias, const float* __restrict__ b_er,
    const float* __restrict__ b_ad, float* __restrict__ out_main)
{
    __shared__ __nv_bfloat16 As[5][64][24];    // 15360 B
    __shared__ __nv_bfloat16 Bs[5][128][24];   // 30720 B  (total 46080 B)

    const int tid = threadIdx.x;
    const int wid = tid >> 5, lane = tid & 31;
    const int m0 = blockIdx.y * 64, n0 = blockIdx.x * 128;
    const int warp_m = wid & 1, warp_n = wid >> 1;     // 2 x 4 warps, tile 32x32

    const uint32_t abase = (uint32_t)__cvta_generic_to_shared(&As[0][0][0]);
    const uint32_t bbase = (uint32_t)__cvta_generic_to_shared(&Bs[0][0][0]);

    // loaders: per 16-K chunk, A = 64 rows x 32 B, B = 128 rows x 32 B
    const int arow = tid >> 1, aseg = tid & 1;         // tid<128 -> A
    const int brow = tid >> 1, bseg = tid & 1;         // all 256 -> B (128 rows x 2 segs)
    const __nv_bfloat16* Ag = A + (size_t)(m0 + arow) * 768 + aseg * 8;
    const __nv_bfloat16* Bg = B + (size_t)(n0 + brow) * 768 + bseg * 8;
    const uint32_t adst = abase + arow * 48 + aseg * 16;
    const uint32_t bdst = bbase + brow * 48 + bseg * 16;

    float acc[2][4][4];
#pragma unroll
    for (int i = 0; i < 2; i++)
#pragma unroll
        for (int j = 0; j < 4; j++)
#pragma unroll
            for (int q = 0; q < 4; q++) acc[i][j][q] = 0.f;

    const int NC = 48;   // 768 / 16
#pragma unroll
    for (int st = 0; st < 4; st++) {
        if (tid < 128) cpasync16(adst + st * 3072, Ag + st * 16);
        cpasync16(bdst + st * 6144, Bg + st * 16);
        cpcommit();
    }

#pragma unroll 1
    for (int c = 0; c < NC; c++) {
        cpwait3();
        __syncthreads();
        const int buf = c % 5;
        const uint32_t ab = abase + buf * 3072;
        const uint32_t bb = bbase + buf * 6144;

        uint32_t af[2][4];
#pragma unroll
        for (int mi = 0; mi < 2; mi++) {
            const int rr = warp_m * 32 + mi * 16 + (lane & 15);
            const int cc = (lane >> 4) << 3;
            ldsm4(af[mi][0], af[mi][1], af[mi][2], af[mi][3],
                  ab + (uint32_t)(rr * 24 + cc) * 2);
        }
        uint32_t bf[2][4];
#pragma unroll
        for (int bi2 = 0; bi2 < 2; bi2++) {
            const int rr = warp_n * 32 + bi2 * 16 + ((lane >> 4) << 3) + (lane & 7);
            const int cc = ((lane >> 3) & 1) << 3;
            ldsm4(bf[bi2][0], bf[bi2][1], bf[bi2][2], bf[bi2][3],
                  bb + (uint32_t)(rr * 24 + cc) * 2);
        }
#pragma unroll
        for (int mi = 0; mi < 2; mi++)
#pragma unroll
            for (int nj = 0; nj < 4; nj++) {
                const uint32_t b0 = bf[nj >> 1][(nj & 1) * 2];
                const uint32_t b1 = bf[nj >> 1][(nj & 1) * 2 + 1];
                mma16816(acc[mi][nj][0], acc[mi][nj][1], acc[mi][nj][2], acc[mi][nj][3],
                         af[mi][0], af[mi][1], af[mi][2], af[mi][3], b0, b1);
            }

        if (c + 4 < NC) {
            const int ns = (c + 4) % 5;
            const int koff = (c + 4) * 16;
            if (tid < 128) cpasync16(adst + ns * 3072, Ag + koff);
            cpasync16(bdst + ns * 6144, Bg + koff);
        }
        // unconditional commit keeps one group per iteration (group accounting)
        cpcommit();
    }

    // ----- epilogue -----
    const int erow = lane >> 2;
    const int ecol = (lane & 3) * 2;
#pragma unroll
    for (int mi = 0; mi < 2; mi++) {
        const int r0 = m0 + warp_m * 32 + mi * 16 + erow;
#pragma unroll
        for (int nj = 0; nj < 4; nj++) {
            const int cbase = n0 + warp_n * 32 + nj * 8 + ecol;
            const float v0 = acc[mi][nj][0], v1 = acc[mi][nj][1];
            const float v2 = acc[mi][nj][2], v3 = acc[mi][nj][3];
            if (MODE == 0) {
                const float bz0 = g_gate_bias[cbase + (cbase >= 256 ? 256 : 0)];
                const float bz1 = g_gate_bias[cbase + 1 + (cbase + 1 >= 256 ? 256 : 0)];
                float* p0 = g_gates + (size_t)r0 * 768 + cbase;
                p0[0] = v0 + bz0; p0[1] = v1 + bz1;
                float* p1 = p0 + 8 * 768;
                p1[0] = v2 + bz0; p1[1] = v3 + bz1;
            } else {
                if (cbase < 1024) {
                    const float bz0 = bias[cbase], bz1 = bias[cbase + 1];
                    float* p0 = g_ww + (size_t)r0 * 1024 + cbase;
                    p0[0] = v0 + bz0; p0[1] = v1 + bz1;
                    float* p1 = p0 + 8 * 1024;
                    p1[0] = v2 + bz0; p1[1] = v3 + bz1;
                } else {
#pragma unroll
                    for (int q = 0; q < 4; q++) {
                        const int m = r0 + (q >= 2 ? 8 : 0);
                        const int n = cbase + (q & 1) - 1024;
                        const float vv = (q == 0) ? v0 : (q == 1) ? v1 : (q == 2) ? v2 : v3;
                        if (n < 32)        g_erase[m * 32 + n] = sigm_fast(vv + b_er[n]);
                        else if (n < 64)   g_add[m * 32 + n - 32] = tanh_fast(vv + b_ad[n - 32]);
                        else if (n < 320)  out_main[(size_t)m * 256 + n - 64] = vv + g_out_bias[n - 64];
                    }
                }
            }
        }
    }
}

// ---------------- k3: LSTM activations (fast MUFU path) -> g_hs --------------
__global__ __launch_bounds__(256) void activ_kernel()
{
    const int idx4 = (blockIdx.x * 256 + threadIdx.x) * 4;   // 2048*256 elems
    const int b = idx4 >> 8, cc = idx4 & 255;
    const float* g = g_gates + (size_t)b * 768 + cc;
    const float4 ig = *(const float4*)(g);
    const float4 gg = *(const float4*)(g + 256);
    const float4 og = *(const float4*)(g + 512);
    float h[4];
    h[0] = sigm_fast(og.x) * tanh_fast(sigm_fast(ig.x) * tanh_fast(gg.x));
    h[1] = sigm_fast(og.y) * tanh_fast(sigm_fast(ig.y) * tanh_fast(gg.y));
    h[2] = sigm_fast(og.z) * tanh_fast(sigm_fast(ig.z) * tanh_fast(gg.z));
    h[3] = sigm_fast(og.w) * tanh_fast(sigm_fast(ig.w) * tanh_fast(gg.w));
    splitA4(g_hs + (size_t)b * 768 + cc, make_float4(h[0], h[1], h[2], h[3]));
}

// ---------------- k5: per-row (max, 1/sumexp) over g_ww [2048 x 1024] --------
__global__ __launch_bounds__(256) void rowstat_kernel()
{
    __shared__ float red[8];
    __shared__ float bc;
    const float4* p = (const float4*)(g_ww + (size_t)blockIdx.x * 1024);
    const int t = threadIdx.x, lane = t & 31, w = t >> 5;
    const float4 v = p[t];
    float mx = fmaxf(fmaxf(v.x, v.y), fmaxf(v.z, v.w));
#pragma unroll
    for (int o = 16; o; o >>= 1) mx = fmaxf(mx, __shfl_xor_sync(FULLMASK, mx, o));
    if (lane == 0) red[w] = mx;
    __syncthreads();
    if (t == 0) { float m = red[0]; for (int i = 1; i < 8; i++) m = fmaxf(m, red[i]); bc = m; }
    __syncthreads();
    mx = bc;
    float s = __expf(v.x - mx) + __expf(v.y - mx) + __expf(v.z - mx) + __expf(v.w - mx);
#pragma unroll
    for (int o = 16; o; o >>= 1) s += __shfl_xor_sync(FULLMASK, s, o);
    __syncthreads();
    if (lane == 0) red[w] = s;
    __syncthreads();
    if (t == 0) {
        float ss = 0.f;
        for (int i = 0; i < 8; i++) ss += red[i];
        g_wstat[blockIdx.x] = make_float2(mx, 1.f / ss);
    }
}

// ---------------- k6: write_data with inline softmax (268 MB stores) ---------
__global__ __launch_bounds__(256) void write_mem3(
    const float* __restrict__ memory, float* __restrict__ outw)
{
    __shared__ float msl[64 * 32];    // memory slice
    __shared__ float wsm[64 * 64];    // normalized weights [batch][row]
    const int m0 = blockIdx.x * 64;
    const int b0 = blockIdx.y * 64;
    const int t = threadIdx.x;

    {
        const float4* src = (const float4*)(memory + m0 * 32);
        float4* dst = (float4*)msl;
        dst[t] = src[t];
        dst[t + 256] = src[t + 256];
    }
    {
        // thread -> (batch = t>>2, rows (t&3)*16 .. +15)
        const int wb = t >> 2;
        const int r0w = (t & 3) * 16;
        const float2 st = g_wstat[b0 + wb];
        const float* lg = g_ww + (size_t)(b0 + wb) * 1024 + m0 + r0w;
        float* wd = wsm + wb * 64 + r0w;
#pragma unroll
        for (int i = 0; i < 16; i++) wd[i] = __expf(lg[i] - st.x) * st.y;
    }
    __syncthreads();

    const int row = t >> 3;
    const int d4 = (t & 7) * 4;
    const float4 mv0 = *(const float4*)&msl[row * 32 + d4];
    const float4 mv1 = *(const float4*)&msl[(row + 32) * 32 + d4];

#pragma unroll 4
    for (int bi = 0; bi < 64; bi++) {
        const int b = b0 + bi;
        const float4 ev = *(const float4*)(g_erase + b * 32 + d4);
        const float4 av = *(const float4*)(g_add + b * 32 + d4);
        const float w0 = wsm[bi * 64 + row];
        const float w1 = wsm[bi * 64 + row + 32];
        float* ob = outw + (size_t)b * 32768 + (size_t)m0 * 32;
        float4 r;
        r.x = mv0.x - w0 * (mv0.x * ev.x - av.x);
        r.y = mv0.y - w0 * (mv0.y * ev.y - av.y);
        r.z = mv0.z - w0 * (mv0.z * ev.z - av.z);
        r.w = mv0.w - w0 * (mv0.w * ev.w - av.w);
        __stcs((float4*)(ob + row * 32 + d4), r);
        r.x = mv1.x - w1 * (mv1.x * ev.x - av.x);
        r.y = mv1.y - w1 * (mv1.y * ev.y - av.y);
        r.z = mv1.z - w1 * (mv1.z * ev.z - av.z);
        r.w = mv1.w - w1 * (mv1.w * ev.w - av.w);
        __stcs((float4*)(ob + (row + 32) * 32 + d4), r);
    }
}

// ---------------- launch -----------------------------------------------------
extern "C" void kernel_launch(void* const* d_in, const int* in_sizes, int n_in,
                              void* d_out, int out_size)
{
    const float* x       = (const float*)d_in[0];
    const float* memory  = (const float*)d_in[1];
    const float* b_rattn = (const float*)d_in[3];
    const float* W_ih    = (const float*)d_in[4];
    const float* b_ih    = (const float*)d_in[6];
    const float* b_hh    = (const float*)d_in[7];
    const float* W_wattn = (const float*)d_in[8];
    const float* b_wattn = (const float*)d_in[9];
    const float* W_er    = (const float*)d_in[10];
    const float* b_er    = (const float*)d_in[11];
    const float* W_ad    = (const float*)d_in[12];
    const float* b_ad    = (const float*)d_in[13];
    const float* W_out   = (const float*)d_in[14];
    const float* b_out   = (const float*)d_in[15];
    float* out = (float*)d_out;

    __nv_bfloat16 *xs, *hs, *Bih, *Bcomb;
    cudaGetSymbolAddress((void**)&xs, g_xs);
    cudaGetSymbolAddress((void**)&hs, g_hs);
    cudaGetSymbolAddress((void**)&Bih, g_Bih);
    cudaGetSymbolAddress((void**)&Bcomb, g_Bcomb);

    conv_all_kernel<<<1056, 256>>>(x, W_ih, W_wattn, W_er, W_ad, W_out);
    setup_kernel<<<1, 256>>>(b_rattn, memory, W_ih, b_ih, b_hh, W_out, b_out);
    mma_gemm<0><<<dim3(6, 32), 256>>>(xs, Bih, nullptr, nullptr, nullptr, nullptr);
    activ_kernel<<<512, 256>>>();
    mma_gemm<1><<<dim3(11, 32), 256>>>(hs, Bcomb, b_wattn, b_er, b_ad, out);
    rowstat_kernel<<<2048, 256>>>();
    write_mem3<<<dim3(16, 32), 256>>>(memory, out + 2048 * 256);
}

// round 11
// speedup vs baseline: 1.0824x; 1.0824x over previous
#include <cuda_runtime.h>
#include <cuda_bf16.h>
#include <cstdint>

#define FULLMASK 0xffffffffu

// ---------------- scratch (device globals; no allocations) -------------------
__device__ float g_ww[2048 * 1024];            // write-attn logits -> weights
__device__ float g_erase[2048 * 32];
__device__ float g_add[2048 * 32];
__device__ float g_gate_bias[1024];            // indexed by ORIGINAL 1024 gate idx
__device__ float g_out_bias[256];

// bf16 split buffers (K expanded 256 -> 768: A=[hi|lo|hi], B=[hi|hi|lo])
__device__ __nv_bfloat16 g_xs[2048 * 768];
__device__ __nv_bfloat16 g_hs[2048 * 768];
__device__ __nv_bfloat16 g_Bih[1024 * 768];    // W_ih rows INTERLEAVED (i,g,o,pad) per channel
__device__ __nv_bfloat16 g_Bcomb[1408 * 768];  // [W_wattn(1024) | W_er|W_ad|W_out|pad]

__device__ __forceinline__ float sigm_fast(float x)
{
    return __fdividef(1.f, 1.f + __expf(-x));
}
__device__ __forceinline__ float tanh_fast(float x)
{
    const float e = __expf(2.f * x);
    return 1.f - __fdividef(2.f, e + 1.f);
}

// ---------------- PTX helpers -------------------------------------------------
__device__ __forceinline__ void ldsm4(uint32_t& r0, uint32_t& r1, uint32_t& r2,
                                      uint32_t& r3, uint32_t addr)
{
    asm volatile("ldmatrix.sync.aligned.m8n8.x4.shared.b16 {%0,%1,%2,%3}, [%4];"
                 : "=r"(r0), "=r"(r1), "=r"(r2), "=r"(r3) : "r"(addr));
}
__device__ __forceinline__ void mma16816(float& d0, float& d1, float& d2, float& d3,
                                         uint32_t a0, uint32_t a1, uint32_t a2, uint32_t a3,
                                         uint32_t b0, uint32_t b1)
{
    asm volatile(
        "mma.sync.aligned.m16n8k16.row.col.f32.bf16.bf16.f32 "
        "{%0,%1,%2,%3}, {%4,%5,%6,%7}, {%8,%9}, {%0,%1,%2,%3};"
        : "+f"(d0), "+f"(d1), "+f"(d2), "+f"(d3)
        : "r"(a0), "r"(a1), "r"(a2), "r"(a3), "r"(b0), "r"(b1));
}
__device__ __forceinline__ void cpasync16(uint32_t dst, const void* src)
{
    asm volatile("cp.async.cg.shared.global [%0], [%1], 16;" :: "r"(dst), "l"(src));
}
__device__ __forceinline__ void cpcommit() { asm volatile("cp.async.commit_group;"); }
__device__ __forceinline__ void cpwait1() { asm volatile("cp.async.wait_group 1;"); }

__device__ __forceinline__ uint32_t packbf2(float a, float b)
{
    __nv_bfloat162 t = __floats2bfloat162_rn(a, b);
    return *reinterpret_cast<uint32_t*>(&t);
}

// ---------------- vectorized split writers ------------------------------------
__device__ __forceinline__ void splitA4(__nv_bfloat16* dst, float4 v)
{
    const float h0 = __bfloat162float(__float2bfloat16_rn(v.x));
    const float h1 = __bfloat162float(__float2bfloat16_rn(v.y));
    const float h2 = __bfloat162float(__float2bfloat16_rn(v.z));
    const float h3 = __bfloat162float(__float2bfloat16_rn(v.w));
    const uint2 hi = make_uint2(packbf2(v.x, v.y), packbf2(v.z, v.w));
    const uint2 lo = make_uint2(packbf2(v.x - h0, v.y - h1), packbf2(v.z - h2, v.w - h3));
    *(uint2*)(dst) = hi;
    *(uint2*)(dst + 256) = lo;
    *(uint2*)(dst + 512) = hi;
}
__device__ __forceinline__ void splitB4(__nv_bfloat16* dst, float4 v)
{
    const float h0 = __bfloat162float(__float2bfloat16_rn(v.x));
    const float h1 = __bfloat162float(__float2bfloat16_rn(v.y));
    const float h2 = __bfloat162float(__float2bfloat16_rn(v.z));
    const float h3 = __bfloat162float(__float2bfloat16_rn(v.w));
    const uint2 hi = make_uint2(packbf2(v.x, v.y), packbf2(v.z, v.w));
    const uint2 lo = make_uint2(packbf2(v.x - h0, v.y - h1), packbf2(v.z - h2, v.w - h3));
    *(uint2*)(dst) = hi;
    *(uint2*)(dst + 256) = hi;
    *(uint2*)(dst + 512) = lo;
}

// ---------------- k1: convert (blocks 0..1119) + setup (block 1120) ----------
__global__ __launch_bounds__(256) void conv_setup_kernel(
    const float* __restrict__ x, const float* __restrict__ W_ih,
    const float* __restrict__ W_wattn, const float* __restrict__ W_er,
    const float* __restrict__ W_ad, const float* __restrict__ W_out,
    const float* __restrict__ b_rattn, const float* __restrict__ memory,
    const float* __restrict__ b_ih, const float* __restrict__ b_hh,
    const float* __restrict__ b_out)
{
    const int t = threadIdx.x;
    if (blockIdx.x < 1120) {
        const int vr = blockIdx.x * 4 + (t >> 6);
        const int k = (t & 63) * 4;
        if (vr < 2048) {
            splitA4(g_xs + (size_t)vr * 768 + k, *(const float4*)(x + (size_t)vr * 256 + k));
        } else if (vr < 3072) {
            // interleaved gate rows: r = 4*c + p, p in {i,g,o,pad}
            const int r = vr - 2048;
            const int c = r >> 2, p = r & 3;
            float4 v = make_float4(0.f, 0.f, 0.f, 0.f);
            if (p == 0)      v = *(const float4*)(W_ih + (size_t)c * 288 + k);          // i
            else if (p == 1) v = *(const float4*)(W_ih + (size_t)(512 + c) * 288 + k);  // g
            else if (p == 2) v = *(const float4*)(W_ih + (size_t)(768 + c) * 288 + k);  // o
            splitB4(g_Bih + (size_t)r * 768 + k, v);
        } else if (vr < 4096) {
            const int rw = vr - 3072;
            splitB4(g_Bcomb + (size_t)rw * 768 + k, *(const float4*)(W_wattn + (size_t)rw * 256 + k));
        } else {
            const int rh = vr - 4096;
            float4 v = make_float4(0.f, 0.f, 0.f, 0.f);
            if (rh < 32)       v = *(const float4*)(W_er + (size_t)rh * 256 + k);
            else if (rh < 64)  v = *(const float4*)(W_ad + (size_t)(rh - 32) * 256 + k);
            else if (rh < 320) v = *(const float4*)(W_out + (size_t)(rh - 64) * 288 + k);
            splitB4(g_Bcomb + (size_t)(1024 + rh) * 768 + k, v);
        }
        return;
    }

    // ---- setup part (single block): softmax(b_rattn), rd, folded biases ----
    __shared__ float wr[1024];
    __shared__ float red[32];
    __shared__ float bc;
    __shared__ float part[8 * 32];
    __shared__ float rd_s[32];
    const int lane = t & 31, w = t >> 5;

    float mx = -1e30f;
    for (int i = t; i < 1024; i += 256) { float v = b_rattn[i]; wr[i] = v; mx = fmaxf(mx, v); }
#pragma unroll
    for (int o = 16; o; o >>= 1) mx = fmaxf(mx, __shfl_xor_sync(FULLMASK, mx, o));
    if (lane == 0) red[w] = mx;
    __syncthreads();
    if (t == 0) { float m = red[0]; for (int i = 1; i < 8; i++) m = fmaxf(m, red[i]); bc = m; }
    __syncthreads();
    mx = bc;
    float s = 0.f;
    for (int i = t; i < 1024; i += 256) { float e = __expf(wr[i] - mx); wr[i] = e; s += e; }
#pragma unroll
    for (int o = 16; o; o >>= 1) s += __shfl_xor_sync(FULLMASK, s, o);
    __syncthreads();
    if (lane == 0) red[w] = s;
    __syncthreads();
    if (t == 0) { float ss = 0.f; for (int i = 0; i < 8; i++) ss += red[i]; bc = ss; }
    __syncthreads();
    const float inv = 1.f / bc;
    for (int i = t; i < 1024; i += 256) wr[i] *= inv;
    __syncthreads();

    {
        const int d = lane, pp = w;
        float acc = 0.f;
        const int m0 = pp * 128;
        for (int m = m0; m < m0 + 128; m++) acc += wr[m] * memory[m * 32 + d];
        part[pp * 32 + d] = acc;
    }
    __syncthreads();
    if (t < 32) { float r = 0.f; for (int p = 0; p < 8; p++) r += part[p * 32 + t]; rd_s[t] = r; }
    __syncthreads();

    for (int j = t; j < 1024; j += 256) {
        float g = b_ih[j] + b_hh[j];
        const float* wp = W_ih + (size_t)j * 288 + 256;
#pragma unroll
        for (int d = 0; d < 32; d++) g += wp[d] * rd_s[d];
        g_gate_bias[j] = g;
    }
    {
        float g = b_out[t];
        const float* wp = W_out + (size_t)t * 288 + 256;
#pragma unroll
        for (int d = 0; d < 32; d++) g += wp[d] * rd_s[d];
        g_out_bias[t] = g;
    }
}

// ---------------- bf16 MMA GEMM: 64(M) x 128(N), K'=768, 3-stage cp.async ----
// MODE 0: A=g_xs, B=g_Bih (N=1024, interleaved i,g,o,pad per channel)
//         epilogue: shuffle-based fused LSTM activation -> split -> g_hs
// MODE 1: A=g_hs, B=g_Bcomb(N=1408), n<1024 -> g_ww + b_wattn; else head scatter
template <int MODE>
__global__ __launch_bounds__(256, 2) void mma_gemm(
    const __nv_bfloat16* __restrict__ A, const __nv_bfloat16* __restrict__ B,
    const float* __restrict__ bias, const float* __restrict__ b_er,
    const float* __restrict__ b_ad, float* __restrict__ out_main)
{
    __shared__ __nv_bfloat16 As[3][64][40];
    __shared__ __nv_bfloat16 Bs[3][128][40];

    const int tid = threadIdx.x;
    const int wid = tid >> 5, lane = tid & 31;
    const int m0 = blockIdx.y * 64, n0 = blockIdx.x * 128;
    const int warp_m = wid & 1, warp_n = wid >> 1;     // 2 x 4 warps, tile 32x32

    const uint32_t abase = (uint32_t)__cvta_generic_to_shared(&As[0][0][0]);
    const uint32_t bbase = (uint32_t)__cvta_generic_to_shared(&Bs[0][0][0]);

    const int lrow = tid >> 2, lseg = tid & 3;
    const __nv_bfloat16* Ag = A + (size_t)(m0 + lrow) * 768 + lseg * 8;
    const __nv_bfloat16* Bg0 = B + (size_t)(n0 + lrow) * 768 + lseg * 8;
    const __nv_bfloat16* Bg1 = Bg0 + (size_t)64 * 768;
    const uint32_t adst = abase + lrow * 80 + lseg * 16;
    const uint32_t bdst0 = bbase + lrow * 80 + lseg * 16;
    const uint32_t bdst1 = bdst0 + 64 * 80;

    float acc[2][4][4];
#pragma unroll
    for (int i = 0; i < 2; i++)
#pragma unroll
        for (int j = 0; j < 4; j++)
#pragma unroll
            for (int q = 0; q < 4; q++) acc[i][j][q] = 0.f;

    const int NC = 24;   // 768/32
#pragma unroll
    for (int st = 0; st < 2; st++) {
        const int koff = st * 32;
        cpasync16(adst + st * 5120, Ag + koff);
        cpasync16(bdst0 + st * 10240, Bg0 + koff);
        cpasync16(bdst1 + st * 10240, Bg1 + koff);
        cpcommit();
    }

#pragma unroll 1
    for (int c = 0; c < NC; c++) {
        cpwait1();
        __syncthreads();
        const int buf = c % 3;
        const uint32_t ab = abase + buf * 5120;
        const uint32_t bb = bbase + buf * 10240;
#pragma unroll
        for (int kk = 0; kk < 2; kk++) {
            const int k16 = kk * 16;
            uint32_t af[2][4];
#pragma unroll
            for (int mi = 0; mi < 2; mi++) {
                const int rr = warp_m * 32 + mi * 16 + (lane & 15);
                const int cc = k16 + ((lane >> 4) << 3);
                ldsm4(af[mi][0], af[mi][1], af[mi][2], af[mi][3],
                      ab + (uint32_t)(rr * 40 + cc) * 2);
            }
            uint32_t bf[2][4];
#pragma unroll
            for (int bi = 0; bi < 2; bi++) {
                const int rr = warp_n * 32 + bi * 16 + ((lane >> 4) << 3) + (lane & 7);
                const int cc = k16 + (((lane >> 3) & 1) << 3);
                ldsm4(bf[bi][0], bf[bi][1], bf[bi][2], bf[bi][3],
                      bb + (uint32_t)(rr * 40 + cc) * 2);
            }
#pragma unroll
            for (int mi = 0; mi < 2; mi++)
#pragma unroll
                for (int nj = 0; nj < 4; nj++) {
                    const uint32_t b0 = bf[nj >> 1][(nj & 1) * 2];
                    const uint32_t b1 = bf[nj >> 1][(nj & 1) * 2 + 1];
                    mma16816(acc[mi][nj][0], acc[mi][nj][1], acc[mi][nj][2], acc[mi][nj][3],
                             af[mi][0], af[mi][1], af[mi][2], af[mi][3], b0, b1);
                }
        }
        if (c + 2 < NC) {
            const int ns = (c + 2) % 3;
            const int koff = (c + 2) * 32;
            cpasync16(adst + ns * 5120, Ag + koff);
            cpasync16(bdst0 + ns * 10240, Bg0 + koff);
            cpasync16(bdst1 + ns * 10240, Bg1 + koff);
        }
        cpcommit();
    }

    // ----- epilogues -----
    const int erow = lane >> 2;
    const int ecol = (lane & 3) * 2;

    if (MODE == 0) {
        // Interleaved layout: cols 4c..4c+3 = (i,g,o,pad) of channel c.
        // Thread with even (lane&1) holds (i,g) at cols cbase,cbase+1;
        // its partner lane^1 holds (o,pad). One shfl_xor delivers o.
#pragma unroll
        for (int mi = 0; mi < 2; mi++) {
            const int r0 = m0 + warp_m * 32 + mi * 16 + erow;
#pragma unroll
            for (int nj = 0; nj < 4; nj++) {
                const int cbase = n0 + warp_n * 32 + nj * 8 + ecol;
                const float ov0 = __shfl_xor_sync(FULLMASK, acc[mi][nj][0], 1);
                const float ov2 = __shfl_xor_sync(FULLMASK, acc[mi][nj][2], 1);
                if ((lane & 1) == 0) {
                    const int ch = cbase >> 2;          // 0..255
                    const float bi_ = g_gate_bias[ch];
                    const float bg_ = g_gate_bias[512 + ch];
                    const float bo_ = g_gate_bias[768 + ch];
                    {
                        const float h = sigm_fast(ov0 + bo_) *
                                        tanh_fast(sigm_fast(acc[mi][nj][0] + bi_) *
                                                  tanh_fast(acc[mi][nj][1] + bg_));
                        const __nv_bfloat16 hi = __float2bfloat16_rn(h);
                        const __nv_bfloat16 lo = __float2bfloat16_rn(h - __bfloat162float(hi));
                        __nv_bfloat16* d = g_hs + (size_t)r0 * 768 + ch;
                        d[0] = hi; d[256] = lo; d[512] = hi;
                    }
                    {
                        const float h = sigm_fast(ov2 + bo_) *
                                        tanh_fast(sigm_fast(acc[mi][nj][2] + bi_) *
                                                  tanh_fast(acc[mi][nj][3] + bg_));
                        const __nv_bfloat16 hi = __float2bfloat16_rn(h);
                        const __nv_bfloat16 lo = __float2bfloat16_rn(h - __bfloat162float(hi));
                        __nv_bfloat16* d = g_hs + (size_t)(r0 + 8) * 768 + ch;
                        d[0] = hi; d[256] = lo; d[512] = hi;
                    }
                }
            }
        }
    } else {
#pragma unroll
        for (int mi = 0; mi < 2; mi++) {
            const int r0 = m0 + warp_m * 32 + mi * 16 + erow;
#pragma unroll
            for (int nj = 0; nj < 4; nj++) {
                const int cbase = n0 + warp_n * 32 + nj * 8 + ecol;
                const float v0 = acc[mi][nj][0], v1 = acc[mi][nj][1];
                const float v2 = acc[mi][nj][2], v3 = acc[mi][nj][3];
                if (cbase < 1024) {
                    const float bz0 = bias[cbase], bz1 = bias[cbase + 1];
                    float* p0 = g_ww + (size_t)r0 * 1024 + cbase;
                    p0[0] = v0 + bz0; p0[1] = v1 + bz1;
                    float* p1 = p0 + 8 * 1024;
                    p1[0] = v2 + bz0; p1[1] = v3 + bz1;
                } else {
#pragma unroll
                    for (int q = 0; q < 4; q++) {
                        const int m = r0 + (q >= 2 ? 8 : 0);
                        const int n = cbase + (q & 1) - 1024;
                        const float vv = (q == 0) ? v0 : (q == 1) ? v1 : (q == 2) ? v2 : v3;
                        if (n < 32)        g_erase[m * 32 + n] = sigm_fast(vv + b_er[n]);
                        else if (n < 64)   g_add[m * 32 + n - 32] = tanh_fast(vv + b_ad[n - 32]);
                        else if (n < 320)  out_main[(size_t)m * 256 + n - 64] = vv + g_out_bias[n - 64];
                    }
                }
            }
        }
    }
}

// ---------------- k5: row softmax over g_ww [2048 x 1024], float4 ------------
__global__ __launch_bounds__(256) void softmax1024()
{
    __shared__ float red[8];
    __shared__ float bc;
    float4* p = (float4*)(g_ww + (size_t)blockIdx.x * 1024);
    const int t = threadIdx.x, lane = t & 31, w = t >> 5;
    float4 v = p[t];
    float mx = fmaxf(fmaxf(v.x, v.y), fmaxf(v.z, v.w));
#pragma unroll
    for (int o = 16; o; o >>= 1) mx = fmaxf(mx, __shfl_xor_sync(FULLMASK, mx, o));
    if (lane == 0) red[w] = mx;
    __syncthreads();
    if (t == 0) { float m = red[0]; for (int i = 1; i < 8; i++) m = fmaxf(m, red[i]); bc = m; }
    __syncthreads();
    mx = bc;
    v.x = __expf(v.x - mx); v.y = __expf(v.y - mx);
    v.z = __expf(v.z - mx); v.w = __expf(v.w - mx);
    float s = v.x + v.y + v.z + v.w;
#pragma unroll
    for (int o = 16; o; o >>= 1) s += __shfl_xor_sync(FULLMASK, s, o);
    __syncthreads();
    if (lane == 0) red[w] = s;
    __syncthreads();
    if (t == 0) { float ss = 0.f; for (int i = 0; i < 8; i++) ss += red[i]; bc = ss; }
    __syncthreads();
    const float inv = 1.f / bc;
    v.x *= inv; v.y *= inv; v.z *= inv; v.w *= inv;
    p[t] = v;
}

// ---------------- k6: write_data, memory-slice reuse (268 MB stores) ---------
__global__ __launch_bounds__(256) void write_mem2(
    const float* __restrict__ memory, float* __restrict__ outw)
{
    __shared__ float msl[64 * 32];
    const int m0 = blockIdx.x * 64;
    const int b0 = blockIdx.y * 64;
    const int t = threadIdx.x;

    {
        const float4* src = (const float4*)(memory + m0 * 32);
        float4* dst = (float4*)msl;
        dst[t] = src[t];
        dst[t + 256] = src[t + 256];
    }
    __syncthreads();

    const int row = t >> 3;
    const int d4 = (t & 7) * 4;
    const float4 mv0 = *(const float4*)&msl[row * 32 + d4];
    const float4 mv1 = *(const float4*)&msl[(row + 32) * 32 + d4];

#pragma unroll 4
    for (int bi = 0; bi < 64; bi++) {
        const int b = b0 + bi;
        const float4 ev = *(const float4*)(g_erase + b * 32 + d4);
        const float4 av = *(const float4*)(g_add + b * 32 + d4);
        const float* wwb = g_ww + (size_t)b * 1024 + m0;
        const float w0 = wwb[row], w1 = wwb[row + 32];
        float* ob = outw + (size_t)b * 32768 + (size_t)m0 * 32;
        float4 r;
        r.x = mv0.x - w0 * (mv0.x * ev.x - av.x);
        r.y = mv0.y - w0 * (mv0.y * ev.y - av.y);
        r.z = mv0.z - w0 * (mv0.z * ev.z - av.z);
        r.w = mv0.w - w0 * (mv0.w * ev.w - av.w);
        __stcs((float4*)(ob + row * 32 + d4), r);
        r.x = mv1.x - w1 * (mv1.x * ev.x - av.x);
        r.y = mv1.y - w1 * (mv1.y * ev.y - av.y);
        r.z = mv1.z - w1 * (mv1.z * ev.z - av.z);
        r.w = mv1.w - w1 * (mv1.w * ev.w - av.w);
        __stcs((float4*)(ob + (row + 32) * 32 + d4), r);
    }
}

// ---------------- launch -----------------------------------------------------
extern "C" void kernel_launch(void* const* d_in, const int* in_sizes, int n_in,
                              void* d_out, int out_size)
{
    const float* x       = (const float*)d_in[0];
    const float* memory  = (const float*)d_in[1];
    const float* b_rattn = (const float*)d_in[3];
    const float* W_ih    = (const float*)d_in[4];
    const float* b_ih    = (const float*)d_in[6];
    const float* b_hh    = (const float*)d_in[7];
    const float* W_wattn = (const float*)d_in[8];
    const float* b_wattn = (const float*)d_in[9];
    const float* W_er    = (const float*)d_in[10];
    const float* b_er    = (const float*)d_in[11];
    const float* W_ad    = (const float*)d_in[12];
    const float* b_ad    = (const float*)d_in[13];
    const float* W_out   = (const float*)d_in[14];
    const float* b_out   = (const float*)d_in[15];
    float* out = (float*)d_out;

    __nv_bfloat16 *xs, *hs, *Bih, *Bcomb;
    cudaGetSymbolAddress((void**)&xs, g_xs);
    cudaGetSymbolAddress((void**)&hs, g_hs);
    cudaGetSymbolAddress((void**)&Bih, g_Bih);
    cudaGetSymbolAddress((void**)&Bcomb, g_Bcomb);

    conv_setup_kernel<<<1121, 256>>>(x, W_ih, W_wattn, W_er, W_ad, W_out,
                                     b_rattn, memory, b_ih, b_hh, b_out);
    mma_gemm<0><<<dim3(8, 32), 256>>>(xs, Bih, nullptr, nullptr, nullptr, nullptr);
    mma_gemm<1><<<dim3(11, 32), 256>>>(hs, Bcomb, b_wattn, b_er, b_ad, out);
    softmax1024<<<2048, 256>>>();
    write_mem2<<<dim3(16, 32), 256>>>(memory, out + 2048 * 256);
}